// round 3
// baseline (speedup 1.0000x reference)
#include <cuda_runtime.h>
#include <math.h>

// ---------------------------------------------------------------------------
// Multi-scale region distillation loss — fused single-pass kernel.
//
// Buffers are identified BY SIZE (robust to metadata ordering):
//   labels = d_in[0]; per distinct feature size, 1st occurrence = f, 2nd = fo;
//   size-1 entries = num_class, num_old_class (in order).
//
// Per pixel: cosine(f_p, fo_p) over C channels; class-binned mean; weighted sum.
// HBM-bound (~356 MB streamed once). Lane-quad channel split (4 lanes share
// 4 pixels, 64 channels each) for 4x thread count -> latency hiding.
// ---------------------------------------------------------------------------

#define NUM_SCALES 4
#define MAXC 32            // class bins (labels >= MAXC / < 0 dropped)
#define LAB_DIM 512
#define THREADS 256
#define SPLIT 4            // channel-split factor (lane quad)

__device__ double g_seg[NUM_SCALES * MAXC];
__device__ float  g_cnt[NUM_SCALES * MAXC];

struct ScaleDesc {
    const float4* f;
    const float4* fo;
    int C;          // channels
    int W;          // spatial width (=H)
    int hw4;        // H*W/4
    int groups;     // B * hw4
    int block_base; // first block id of this scale
    int sub;        // LAB_DIM / H
};
struct AllDesc { ScaleDesc s[NUM_SCALES]; };

__global__ void msrd_zero_kernel() {
    int i = threadIdx.x;
    if (i < NUM_SCALES * MAXC) { g_seg[i] = 0.0; g_cnt[i] = 0.0f; }
}

__global__ void __launch_bounds__(THREADS)
msrd_main_kernel(AllDesc d, const int* __restrict__ lab)
{
    __shared__ float s_seg[MAXC];
    __shared__ float s_cnt[MAXC];
    if (threadIdx.x < MAXC) { s_seg[threadIdx.x] = 0.f; s_cnt[threadIdx.x] = 0.f; }
    __syncthreads();

    int sidx;
    if      ((int)blockIdx.x < d.s[1].block_base) sidx = 0;
    else if ((int)blockIdx.x < d.s[2].block_base) sidx = 1;
    else if ((int)blockIdx.x < d.s[3].block_base) sidx = 2;
    else                                          sidx = 3;
    const ScaleDesc sd = d.s[sidx];

    const int lblk  = (int)blockIdx.x - sd.block_base;
    const int t     = lblk * (THREADS / SPLIT) + ((int)threadIdx.x >> 2); // pixel group
    const int split = threadIdx.x & (SPLIT - 1);
    const bool valid = (t < sd.groups);

    float dot0 = 0.f, dot1 = 0.f, dot2 = 0.f, dot3 = 0.f;
    float na0  = 0.f, na1  = 0.f, na2  = 0.f, na3  = 0.f;
    float nb0  = 0.f, nb1  = 0.f, nb2  = 0.f, nb3  = 0.f;

    int b = 0, pg = 0;
    if (valid) {
        b  = t / sd.hw4;
        pg = t - b * sd.hw4;
        const int Cq = sd.C >> 2;   // channels per split lane (64)
        const float4* __restrict__ fp  =
            sd.f  + (size_t)b * sd.C * sd.hw4 + (size_t)split * Cq * sd.hw4 + pg;
        const float4* __restrict__ fop =
            sd.fo + (size_t)b * sd.C * sd.hw4 + (size_t)split * Cq * sd.hw4 + pg;

        #pragma unroll 8
        for (int c = 0; c < Cq; ++c) {
            const float4 a = fp [(size_t)c * sd.hw4];
            const float4 o = fop[(size_t)c * sd.hw4];
            dot0 = fmaf(a.x, o.x, dot0); na0 = fmaf(a.x, a.x, na0); nb0 = fmaf(o.x, o.x, nb0);
            dot1 = fmaf(a.y, o.y, dot1); na1 = fmaf(a.y, a.y, na1); nb1 = fmaf(o.y, o.y, nb1);
            dot2 = fmaf(a.z, o.z, dot2); na2 = fmaf(a.z, a.z, na2); nb2 = fmaf(o.z, o.z, nb2);
            dot3 = fmaf(a.w, o.w, dot3); na3 = fmaf(a.w, a.w, na3); nb3 = fmaf(o.w, o.w, nb3);
        }
    }

    // combine partial sums across the lane quad (xor 1, xor 2)
    const unsigned m = 0xffffffffu;
    #define MSRD_RED(v) \
        v += __shfl_xor_sync(m, v, 1); \
        v += __shfl_xor_sync(m, v, 2);
    MSRD_RED(dot0) MSRD_RED(dot1) MSRD_RED(dot2) MSRD_RED(dot3)
    MSRD_RED(na0)  MSRD_RED(na1)  MSRD_RED(na2)  MSRD_RED(na3)
    MSRD_RED(nb0)  MSRD_RED(nb1)  MSRD_RED(nb2)  MSRD_RED(nb3)
    #undef MSRD_RED

    if (valid && split == 0) {
        const int p = pg << 2;
        const int h = p / sd.W;
        const int w = p - h * sd.W;
        const int* __restrict__ lrow =
            lab + (size_t)b * LAB_DIM * LAB_DIM + (size_t)(h * sd.sub) * LAB_DIM;

        float dots[4] = {dot0, dot1, dot2, dot3};
        float nas [4] = {na0,  na1,  na2,  na3 };
        float nbs [4] = {nb0,  nb1,  nb2,  nb3 };

        #pragma unroll
        for (int i = 0; i < 4; ++i) {
            const float nf  = fmaxf(sqrtf(nas[i]), 1e-8f);
            const float nfo = fmaxf(sqrtf(nbs[i]), 1e-8f);
            const float sim = dots[i] / (nf * nfo);
            const int   l   = lrow[(w + i) * sd.sub];
            if (l >= 0 && l < MAXC) {
                atomicAdd(&s_seg[l], sim);
                atomicAdd(&s_cnt[l], 1.0f);
            }
        }
    }

    __syncthreads();
    if (threadIdx.x < MAXC) {
        const float cs = s_cnt[threadIdx.x];
        if (cs != 0.0f) {
            atomicAdd(&g_seg[sidx * MAXC + threadIdx.x], (double)s_seg[threadIdx.x]);
            atomicAdd(&g_cnt[sidx * MAXC + threadIdx.x], cs);
        }
    }
}

__global__ void msrd_finalize_kernel(const int* __restrict__ ncls_p,
                                     const int* __restrict__ nold_p,
                                     int nc_fallback, int no_fallback,
                                     float* __restrict__ out)
{
    if (threadIdx.x != 0 || blockIdx.x != 0) return;
    const int nc = ncls_p ? *ncls_p : nc_fallback;
    const int no = nold_p ? *nold_p : no_fallback;
    const double wts[NUM_SCALES] = {1.0, 2.0, 3.0, 4.0};

    double loss = 0.0;
    for (int s = 0; s < NUM_SCALES; ++s) {
        for (int cls = 0; cls < nc && cls < MAXC; ++cls) {
            const float cnt = g_cnt[s * MAXC + cls];
            if (cnt > 0.0f) {
                const double mean = g_seg[s * MAXC + cls] / (double)cnt;
                double factor;
                if (cls == 0)        factor = (double)no / (double)nc;
                else if (cls <= no)  factor = 1.0;
                else                 factor = 0.0;
                loss += wts[s] * factor * (1.0 - mean);
            }
        }
    }
    *out = (float)loss;
}

extern "C" void kernel_launch(void* const* d_in, const int* in_sizes, int n_in,
                              void* d_out, int out_size)
{
    const int* lab = (const int*)d_in[0];
    const int B = in_sizes[0] / (LAB_DIM * LAB_DIM);

    // ---- identify feature buffers by size (order-agnostic) ----
    const float* fbuf[NUM_SCALES]  = {nullptr, nullptr, nullptr, nullptr};
    const float* fobuf[NUM_SCALES] = {nullptr, nullptr, nullptr, nullptr};
    long         szs[NUM_SCALES]   = {0, 0, 0, 0};
    int ns = 0;
    const int* scalar_ptrs[2] = {nullptr, nullptr};
    int nscalar = 0;

    for (int i = 1; i < n_in; ++i) {
        const long sz = in_sizes[i];
        if (sz <= 1) {
            if (nscalar < 2) scalar_ptrs[nscalar++] = (const int*)d_in[i];
            continue;
        }
        int j = 0;
        while (j < ns && szs[j] != sz) ++j;
        if (j == ns && ns < NUM_SCALES) {
            szs[ns] = sz; fbuf[ns] = (const float*)d_in[i]; ++ns;
        } else if (j < ns) {
            fobuf[j] = (const float*)d_in[i];
        }
    }
    // sort descending by size (scale 0 = largest)
    for (int i = 0; i < ns; ++i)
        for (int j = i + 1; j < ns; ++j)
            if (szs[j] > szs[i]) {
                long ts = szs[i]; szs[i] = szs[j]; szs[j] = ts;
                const float* tf = fbuf[i]; fbuf[i] = fbuf[j]; fbuf[j] = tf;
                const float* to = fobuf[i]; fobuf[i] = fobuf[j]; fobuf[j] = to;
            }

    // ---- build per-scale descriptors + fused grid ----
    AllDesc ad;
    int block_base = 0;
    for (int s = 0; s < NUM_SCALES; ++s) {
        const int HW_dim = 128 >> s;             // 128,64,32,16
        const int hw4    = (HW_dim * HW_dim) >> 2;
        const int C      = (int)(szs[s] / ((long)B * HW_dim * HW_dim));
        const int groups = B * hw4;
        const int gpb    = THREADS / SPLIT;      // pixel groups per block
        const int nblk   = (groups + gpb - 1) / gpb;

        ad.s[s].f          = (const float4*)fbuf[s];
        ad.s[s].fo         = (const float4*)fobuf[s];
        ad.s[s].C          = C;
        ad.s[s].W          = HW_dim;
        ad.s[s].hw4        = hw4;
        ad.s[s].groups     = groups;
        ad.s[s].block_base = block_base;
        ad.s[s].sub        = LAB_DIM / HW_dim;
        block_base += nblk;
    }

    msrd_zero_kernel<<<1, 128>>>();
    msrd_main_kernel<<<block_base, THREADS>>>(ad, lab);
    msrd_finalize_kernel<<<1, 32>>>(scalar_ptrs[0], scalar_ptrs[1], 21, 15,
                                    (float*)d_out);
}